// round 7
// baseline (speedup 1.0000x reference)
#include <cuda_runtime.h>
#include <cuda_bf16.h>

#define NPTS   65536
#define CHN    256
#define BATCH  16
#define LOUT   8192
#define LOG2L  13

// ----------------------------------------------------------- main gather ---
// Single kernel. blocks [0, PT_BLOCKS): points gather.
//                blocks [PT_BLOCKS, PT_BLOCKS+8192): feature gather-transpose.
// Each block derives its (off, cnt) via two inline binary searches over the
// sorted batch array (threads 0/1) -> no separate boundary kernel, no launch.
//
// Feature mapping (R5, best measured): thread owns channels [4c4,4c4+4) x
// j in [4jq, 4jq+4). Warp lanes = consecutive jq -> 512B contiguous STG.128.
// Loads: 4 independent LDG.128 (scattered rows, ~2 unique due to ~2x upsample,
// L1/L2 absorb duplicates).
#define PT_BLOCKS 128

__global__ __launch_bounds__(256)
void gather_kernel(const float* __restrict__ px,
                   const float4* __restrict__ feat4,
                   const int* __restrict__ batch,
                   float* __restrict__ out_point,
                   float* __restrict__ out_feat) {
    __shared__ int s_bound[2];
    int bid = blockIdx.x;
    int tid = threadIdx.x;

    // Block-uniform batch id.
    int b = (bid < PT_BLOCKS) ? (bid >> 3)                 // 8 point blocks per b
                              : ((bid - PT_BLOCKS) >> 9);  // 512 feat blocks per b

    // lower_bound(batch, b + tid) for tid in {0,1}; batch sorted, vals in [0,16).
    if (tid < 2) {
        int key = b + tid;
        int lo = 0, hi = NPTS;
        #pragma unroll
        for (int it = 0; it < 17; it++) {
            if (lo >= hi) break;
            int mid = (lo + hi) >> 1;
            if (__ldg(&batch[mid]) < key) lo = mid + 1; else hi = mid;
        }
        s_bound[tid] = lo;
    }
    __syncthreads();
    int off = s_bound[0];
    int cnt = s_bound[1] - off;

    if (bid < PT_BLOCKS) {
        // ---- points: thread = 4 consecutive j of one b; float4 writes.
        int idx = bid * 256 + tid;            // 0..32767
        int j = (idx & 2047) * 4;
        float4 ox, oy, oz;
        #pragma unroll
        for (int t = 0; t < 4; t++) {
            int src = off + (int)(((unsigned)((j + t) * cnt)) >> LOG2L);
            const float* p = px + 3 * src;
            ((float*)&ox)[t] = p[0];
            ((float*)&oy)[t] = p[1];
            ((float*)&oz)[t] = p[2];
        }
        size_t base = (size_t)b * 3 * LOUT + j;
        __stcs((float4*)(out_point + base),            ox);
        __stcs((float4*)(out_point + base + LOUT),     oy);
        __stcs((float4*)(out_point + base + 2 * LOUT), oz);
        return;
    }

    // ---- features ----
    int idx = (bid - PT_BLOCKS) * 256 + tid;  // 0 .. 2097151
    int jq = idx & 2047;
    int c4 = (idx >> 11) & 63;
    int j0 = jq * 4;

    float4 v0 = __ldg(feat4 + (size_t)(off + (int)(((unsigned)((j0 + 0) * cnt)) >> LOG2L)) * (CHN / 4) + c4);
    float4 v1 = __ldg(feat4 + (size_t)(off + (int)(((unsigned)((j0 + 1) * cnt)) >> LOG2L)) * (CHN / 4) + c4);
    float4 v2 = __ldg(feat4 + (size_t)(off + (int)(((unsigned)((j0 + 2) * cnt)) >> LOG2L)) * (CHN / 4) + c4);
    float4 v3 = __ldg(feat4 + (size_t)(off + (int)(((unsigned)((j0 + 3) * cnt)) >> LOG2L)) * (CHN / 4) + c4);

    // 4x4 register transpose + coalesced float4 stores (channels 4c4..4c4+3).
    float* ob = out_feat + ((size_t)b * CHN + 4 * c4) * LOUT + j0;
    float4 o;
    o.x = v0.x; o.y = v1.x; o.z = v2.x; o.w = v3.x;
    __stcs((float4*)(ob + 0 * LOUT), o);
    o.x = v0.y; o.y = v1.y; o.z = v2.y; o.w = v3.y;
    __stcs((float4*)(ob + 1 * LOUT), o);
    o.x = v0.z; o.y = v1.z; o.z = v2.z; o.w = v3.z;
    __stcs((float4*)(ob + 2 * LOUT), o);
    o.x = v0.w; o.y = v1.w; o.z = v2.w; o.w = v3.w;
    __stcs((float4*)(ob + 3 * LOUT), o);
}

// ------------------------------------------------------------- launch ------
extern "C" void kernel_launch(void* const* d_in, const int* in_sizes, int n_in,
                              void* d_out, int out_size) {
    const float* points_x = (const float*)d_in[0];   // [N,3]
    const float* feat     = (const float*)d_in[1];   // [N,C]
    const int*   batch    = (const int*)d_in[2];     // [N]

    float* out_point = (float*)d_out;                              // [B,3,L]
    float* out_feat  = (float*)d_out + (size_t)BATCH * 3 * LOUT;   // [B,C,L]

    gather_kernel<<<PT_BLOCKS + 8192, 256>>>(points_x, (const float4*)feat,
                                             batch, out_point, out_feat);
}

// round 8
// speedup vs baseline: 1.4375x; 1.4375x over previous
#include <cuda_runtime.h>
#include <cuda_bf16.h>

#define NPTS   65536
#define CHN    256
#define BATCH  16
#define LOUT   8192
#define LOG2L  13

// g_off[b] = first index with batch id >= b; g_off[BATCH] = NPTS.
__device__ int g_off[BATCH + 1];

// ------------------------------------------------------- boundary detect ---
// batch sorted; int4 loads, boundary write-out, no atomics. (R5 version)
__global__ void boundary_kernel(const int* __restrict__ batch) {
    int t = blockIdx.x * blockDim.x + threadIdx.x;   // 0 .. NPTS/4-1
    if (t >= NPTS / 4) return;
    int4 v = ((const int4*)batch)[t];
    int prev = (t == 0) ? -1 : __ldg(&batch[4 * t - 1]);
    for (int bb = prev + 1; bb <= v.x; bb++) g_off[bb] = 4 * t + 0;
    for (int bb = v.x + 1;  bb <= v.y; bb++) g_off[bb] = 4 * t + 1;
    for (int bb = v.y + 1;  bb <= v.z; bb++) g_off[bb] = 4 * t + 2;
    for (int bb = v.z + 1;  bb <= v.w; bb++) g_off[bb] = 4 * t + 3;
    if (t == NPTS / 4 - 1)
        for (int bb = v.w + 1; bb <= BATCH; bb++) g_off[bb] = NPTS;
}

// ----------------------------------------------------------- main gather ---
// R5 structure. Feature path adds load dedup: src(j0..j0+3) is monotone; load
// endpoint rows always, interior rows only via predicated fallback (rare at
// ~2x upsample). Cuts L1 load wavefronts ~2x; stores unchanged (512B warp-
// contiguous STG.128).
#define PT_BLOCKS 128

__global__ __launch_bounds__(256)
void gather_kernel(const float* __restrict__ px,
                   const float4* __restrict__ feat4,
                   float* __restrict__ out_point,
                   float* __restrict__ out_feat) {
    __shared__ int s_off, s_cnt;
    int bid = blockIdx.x;
    int tid = threadIdx.x;

    if (bid < PT_BLOCKS) {
        int idx = bid * 256 + tid;            // 0..32767
        int b = idx >> 11;
        if (tid == 0) { s_off = g_off[b]; s_cnt = g_off[b + 1] - g_off[b]; }
        __syncthreads();
        int off = s_off, cnt = s_cnt;
        int j = (idx & 2047) * 4;
        float4 ox, oy, oz;
        #pragma unroll
        for (int t = 0; t < 4; t++) {
            int src = off + (int)(((unsigned)((j + t) * cnt)) >> LOG2L);
            const float* p = px + 3 * src;
            ((float*)&ox)[t] = p[0];
            ((float*)&oy)[t] = p[1];
            ((float*)&oz)[t] = p[2];
        }
        size_t base = (size_t)b * 3 * LOUT + j;
        __stcs((float4*)(out_point + base),            ox);
        __stcs((float4*)(out_point + base + LOUT),     oy);
        __stcs((float4*)(out_point + base + 2 * LOUT), oz);
        return;
    }

    // ---- features ----
    int idx = (bid - PT_BLOCKS) * 256 + tid;  // 0 .. 2097151
    int jq = idx & 2047;
    int c4 = (idx >> 11) & 63;
    int b  = idx >> 17;                       // block-uniform
    if (tid == 0) { s_off = g_off[b]; s_cnt = g_off[b + 1] - g_off[b]; }
    __syncthreads();
    int off = s_off, cnt = s_cnt;
    int j0 = jq * 4;

    // Monotone source rows r0 <= r1 <= r2 <= r3.
    int r0 = off + (int)(((unsigned)((j0 + 0) * cnt)) >> LOG2L);
    int r1 = off + (int)(((unsigned)((j0 + 1) * cnt)) >> LOG2L);
    int r2 = off + (int)(((unsigned)((j0 + 2) * cnt)) >> LOG2L);
    int r3 = off + (int)(((unsigned)((j0 + 3) * cnt)) >> LOG2L);

    const float4* fb = feat4 + c4;
    float4 A = __ldg(fb + (size_t)r0 * (CHN / 4));   // always
    float4 D = __ldg(fb + (size_t)r3 * (CHN / 4));   // always
    // v1: equals A (r1==r0) or D (r1==r3), else rare interior load.
    float4 v1 = (r1 == r0) ? A : D;
    if (r1 > r0 && r1 < r3) v1 = __ldg(fb + (size_t)r1 * (CHN / 4));
    float4 v2 = (r2 == r3) ? D : A;
    if (r2 > r0 && r2 < r3) v2 = __ldg(fb + (size_t)r2 * (CHN / 4));

    // 4x4 register transpose + coalesced float4 stores (channels 4c4..4c4+3).
    float* ob = out_feat + ((size_t)b * CHN + 4 * c4) * LOUT + j0;
    float4 o;
    o.x = A.x;  o.y = v1.x; o.z = v2.x; o.w = D.x;
    __stcs((float4*)(ob + 0 * LOUT), o);
    o.x = A.y;  o.y = v1.y; o.z = v2.y; o.w = D.y;
    __stcs((float4*)(ob + 1 * LOUT), o);
    o.x = A.z;  o.y = v1.z; o.z = v2.z; o.w = D.z;
    __stcs((float4*)(ob + 2 * LOUT), o);
    o.x = A.w;  o.y = v1.w; o.z = v2.w; o.w = D.w;
    __stcs((float4*)(ob + 3 * LOUT), o);
}

// ------------------------------------------------------------- launch ------
extern "C" void kernel_launch(void* const* d_in, const int* in_sizes, int n_in,
                              void* d_out, int out_size) {
    const float* points_x = (const float*)d_in[0];   // [N,3]
    const float* feat     = (const float*)d_in[1];   // [N,C]
    const int*   batch    = (const int*)d_in[2];     // [N]

    float* out_point = (float*)d_out;                              // [B,3,L]
    float* out_feat  = (float*)d_out + (size_t)BATCH * 3 * LOUT;   // [B,C,L]

    boundary_kernel<<<64, 256>>>(batch);

    gather_kernel<<<PT_BLOCKS + 8192, 256>>>(points_x, (const float4*)feat,
                                             out_point, out_feat);
}

// round 9
// speedup vs baseline: 1.4568x; 1.0135x over previous
#include <cuda_runtime.h>
#include <cuda_bf16.h>

#define NPTS   65536
#define CHN    256
#define BATCH  16
#define LOUT   8192
#define LOG2L  13

// g_off[b] = first index with batch id >= b; g_off[BATCH] = NPTS.
__device__ int g_off[BATCH + 1];

// ------------------------------------------------------- boundary detect ---
// batch sorted; int4 loads, boundary write-out, no atomics.
// Fires the PDL trigger at entry so the gather grid launches concurrently.
__global__ void boundary_kernel(const int* __restrict__ batch) {
    asm volatile("griddepcontrol.launch_dependents;");
    int t = blockIdx.x * blockDim.x + threadIdx.x;   // 0 .. NPTS/4-1
    if (t >= NPTS / 4) return;
    int4 v = ((const int4*)batch)[t];
    int prev = (t == 0) ? -1 : __ldg(&batch[4 * t - 1]);
    for (int bb = prev + 1; bb <= v.x; bb++) g_off[bb] = 4 * t + 0;
    for (int bb = v.x + 1;  bb <= v.y; bb++) g_off[bb] = 4 * t + 1;
    for (int bb = v.y + 1;  bb <= v.z; bb++) g_off[bb] = 4 * t + 2;
    for (int bb = v.z + 1;  bb <= v.w; bb++) g_off[bb] = 4 * t + 3;
    if (t == NPTS / 4 - 1)
        for (int bb = v.w + 1; bb <= BATCH; bb++) g_off[bb] = NPTS;
}

// ----------------------------------------------------------- main gather ---
// R8 body (best measured). griddepcontrol.wait before reading g_off; all
// g_off-independent prolog (index math) happens before the wait.
#define PT_BLOCKS 128

__global__ __launch_bounds__(256)
void gather_kernel(const float* __restrict__ px,
                   const float4* __restrict__ feat4,
                   float* __restrict__ out_point,
                   float* __restrict__ out_feat) {
    __shared__ int s_off, s_cnt;
    int bid = blockIdx.x;
    int tid = threadIdx.x;

    if (bid < PT_BLOCKS) {
        int idx = bid * 256 + tid;            // 0..32767
        int b = idx >> 11;
        int j = (idx & 2047) * 4;
        asm volatile("griddepcontrol.wait;");
        if (tid == 0) { s_off = g_off[b]; s_cnt = g_off[b + 1] - g_off[b]; }
        __syncthreads();
        int off = s_off, cnt = s_cnt;
        float4 ox, oy, oz;
        #pragma unroll
        for (int t = 0; t < 4; t++) {
            int src = off + (int)(((unsigned)((j + t) * cnt)) >> LOG2L);
            const float* p = px + 3 * src;
            ((float*)&ox)[t] = p[0];
            ((float*)&oy)[t] = p[1];
            ((float*)&oz)[t] = p[2];
        }
        size_t base = (size_t)b * 3 * LOUT + j;
        __stcs((float4*)(out_point + base),            ox);
        __stcs((float4*)(out_point + base + LOUT),     oy);
        __stcs((float4*)(out_point + base + 2 * LOUT), oz);
        return;
    }

    // ---- features ----
    int idx = (bid - PT_BLOCKS) * 256 + tid;  // 0 .. 2097151
    int jq = idx & 2047;
    int c4 = (idx >> 11) & 63;
    int b  = idx >> 17;                       // block-uniform
    int j0 = jq * 4;
    asm volatile("griddepcontrol.wait;");
    if (tid == 0) { s_off = g_off[b]; s_cnt = g_off[b + 1] - g_off[b]; }
    __syncthreads();
    int off = s_off, cnt = s_cnt;

    // Monotone source rows r0 <= r1 <= r2 <= r3; load endpoints, select/rare-
    // load interiors (~2x upsample => usually 2 unique rows).
    int r0 = off + (int)(((unsigned)((j0 + 0) * cnt)) >> LOG2L);
    int r1 = off + (int)(((unsigned)((j0 + 1) * cnt)) >> LOG2L);
    int r2 = off + (int)(((unsigned)((j0 + 2) * cnt)) >> LOG2L);
    int r3 = off + (int)(((unsigned)((j0 + 3) * cnt)) >> LOG2L);

    const float4* fb = feat4 + c4;
    float4 A = __ldg(fb + (size_t)r0 * (CHN / 4));
    float4 D = __ldg(fb + (size_t)r3 * (CHN / 4));
    float4 v1 = (r1 == r0) ? A : D;
    if (r1 > r0 && r1 < r3) v1 = __ldg(fb + (size_t)r1 * (CHN / 4));
    float4 v2 = (r2 == r3) ? D : A;
    if (r2 > r0 && r2 < r3) v2 = __ldg(fb + (size_t)r2 * (CHN / 4));

    float* ob = out_feat + ((size_t)b * CHN + 4 * c4) * LOUT + j0;
    float4 o;
    o.x = A.x;  o.y = v1.x; o.z = v2.x; o.w = D.x;
    __stcs((float4*)(ob + 0 * LOUT), o);
    o.x = A.y;  o.y = v1.y; o.z = v2.y; o.w = D.y;
    __stcs((float4*)(ob + 1 * LOUT), o);
    o.x = A.z;  o.y = v1.z; o.z = v2.z; o.w = D.z;
    __stcs((float4*)(ob + 2 * LOUT), o);
    o.x = A.w;  o.y = v1.w; o.z = v2.w; o.w = D.w;
    __stcs((float4*)(ob + 3 * LOUT), o);
}

// ------------------------------------------------------------- launch ------
extern "C" void kernel_launch(void* const* d_in, const int* in_sizes, int n_in,
                              void* d_out, int out_size) {
    const float* points_x = (const float*)d_in[0];   // [N,3]
    const float* feat     = (const float*)d_in[1];   // [N,C]
    const int*   batch    = (const int*)d_in[2];     // [N]

    float* out_point = (float*)d_out;                              // [B,3,L]
    float* out_feat  = (float*)d_out + (size_t)BATCH * 3 * LOUT;   // [B,C,L]

    boundary_kernel<<<64, 256>>>(batch);

    // Gather launched as a programmatic dependent of boundary_kernel:
    // it launches while boundary runs and blocks at griddepcontrol.wait.
    cudaLaunchConfig_t cfg = {};
    cfg.gridDim  = dim3(PT_BLOCKS + 8192, 1, 1);
    cfg.blockDim = dim3(256, 1, 1);
    cfg.dynamicSmemBytes = 0;
    cfg.stream = 0;
    cudaLaunchAttribute attr[1];
    attr[0].id = cudaLaunchAttributeProgrammaticStreamSerialization;
    attr[0].val.programmaticStreamSerializationAllowed = 1;
    cfg.attrs = attr;
    cfg.numAttrs = 1;
    cudaLaunchKernelEx(&cfg, gather_kernel,
                       points_x, (const float4*)feat, out_point, out_feat);
}